// round 16
// baseline (speedup 1.0000x reference)
#include <cuda_runtime.h>
#include <cuda_fp16.h>
#include <math.h>

// Problem constants
#define Bz 512
#define Tt 200
#define Dd 128
#define Hh 512
#define BT (Bz * Tt)          // 102400
#define COMB 768
#define NBLK 128              // persistent grid: 1 block/SM

// ---------------- scratch (static device globals) ----------------
__device__ __half g_Axh [BT * 256];       // [x_imp || mask], fp16
__device__ __half g_Adh [BT * 128];       // Delta, fp16
__device__ float  g_P  [BT * 1536];       // gate pre-acts (fp32)
__device__ float  g_DH [BT * Hh];         // delta_h (fp32)
__device__ __half g_Wph [1536 * 256];     // packed [x;m] weights, n-major [n][k]
__device__ float  g_Pb [1536];
__device__ __half g_Wghth[512 * 128];     // W_gh, n-major [n][k]
__device__ __half g_Wzrh [1024 * 512];    // h-part W_z|W_r, n-major
__device__ __half g_Whhh [512 * 512];     // h-part W_h, n-major
__device__ float  g_Z  [Bz * Hh];         // z gate (fp32)
__device__ __half g_RHh[Bz * Hh];         // r*(dh*h), fp16
__device__ __half g_HZh[Bz * Hh];         // dh_t * h_{t-1}, fp16
__device__ float  g_h  [Bz * Hh];         // hidden state (exact fp32)

// ---------------- helpers ----------------
__device__ __forceinline__ void mma16(float* d, const unsigned* a, const unsigned* b) {
    asm volatile(
        "mma.sync.aligned.m16n8k16.row.col.f32.f16.f16.f32 "
        "{%0,%1,%2,%3},{%4,%5,%6,%7},{%8,%9},{%0,%1,%2,%3};"
        : "+f"(d[0]), "+f"(d[1]), "+f"(d[2]), "+f"(d[3])
        : "r"(a[0]), "r"(a[1]), "r"(a[2]), "r"(a[3]),
          "r"(b[0]), "r"(b[1]));
}
__device__ __forceinline__ void ldm4(unsigned* r, unsigned addr) {
    asm volatile("ldmatrix.sync.aligned.m8n8.x4.shared.b16 {%0,%1,%2,%3}, [%4];"
        : "=r"(r[0]), "=r"(r[1]), "=r"(r[2]), "=r"(r[3]) : "r"(addr));
}
__device__ __forceinline__ unsigned sm_addr(const void* p) {
    unsigned a;
    asm("{.reg .u64 t; cvta.to.shared.u64 t, %1; cvt.u32.u64 %0, t;}" : "=r"(a) : "l"(p));
    return a;
}
#define CP_A16(dst, src) asm volatile("cp.async.ca.shared.global [%0], [%1], 16;" :: "r"(dst), "l"(src))
#define CP_COMMIT()      asm volatile("cp.async.commit_group;")
#define CP_WAIT2()       asm volatile("cp.async.wait_group 2;")
#define CP_WAIT1()       asm volatile("cp.async.wait_group 1;")
#define CP_WAIT0()       asm volatile("cp.async.wait_group 0;")
#define CLUSTER_SYNC() do { \
    asm volatile("barrier.cluster.arrive.aligned;" ::: "memory"); \
    asm volatile("barrier.cluster.wait.aligned;"   ::: "memory"); \
} while (0)

// prefetch one 32x64(half) activation k-tile into As stage s (stride 72 halves)
__device__ __forceinline__ void pre_tile32h(unsigned asb, int s, int kb,
                                            const __half* __restrict__ src,
                                            int m0, int tid) {
    int r = tid >> 3, c = (tid & 7) * 8;
    CP_A16(asb + (unsigned)(((s * 32 + r) * 72 + c) * 2),
           &src[(size_t)(m0 + r) * 512 + kb + c]);
    CP_COMMIT();
}

// ---------------- weight packing (fp16, n-major) + state init ----------------
__global__ void k_pack(const float* __restrict__ W_z, const float* __restrict__ b_z,
                       const float* __restrict__ W_r, const float* __restrict__ b_r,
                       const float* __restrict__ W_h, const float* __restrict__ b_h,
                       const float* __restrict__ W_gh)
{
    int tid = blockIdx.x * blockDim.x + threadIdx.x;
    int nt  = gridDim.x * blockDim.x;

    for (int idx = tid; idx < 1536 * 256; idx += nt) {
        int n = idx >> 8, k = idx & 255;
        int gsel = n >> 9, jj = n & 511;
        const float* W = (gsel == 0) ? W_z : (gsel == 1) ? W_r : W_h;
        int col = (k < 128) ? k : (640 + (k - 128));
        g_Wph[idx] = __float2half(W[jj * COMB + col]);
    }
    for (int j = tid; j < 1536; j += nt) {
        int gsel = j >> 9, jj = j & 511;
        g_Pb[j] = (gsel == 0) ? b_z[jj] : (gsel == 1) ? b_r[jj] : b_h[jj];
    }
    for (int idx = tid; idx < 512 * 128; idx += nt)
        g_Wghth[idx] = __float2half(W_gh[idx]);           // already [n][k]
    for (int idx = tid; idx < 1024 * 512; idx += nt) {
        int n = idx >> 9, k = idx & 511;
        g_Wzrh[idx] = __float2half((n < 512) ? W_z[n * COMB + 128 + k]
                                             : W_r[(n - 512) * COMB + 128 + k]);
    }
    for (int idx = tid; idx < 512 * 512; idx += nt) {
        int n = idx >> 9, k = idx & 511;
        g_Whhh[idx] = __float2half(W_h[n * COMB + 128 + k]);
    }
    for (int idx = tid; idx < Bz * Hh; idx += nt) {
        g_h[idx] = 0.f;
        g_HZh[idx] = __float2half(0.f);
    }
}

// ---------------- imputation (fp16 stores) ----------------
__global__ void k_impute(const float* __restrict__ X,  const float* __restrict__ XL,
                         const float* __restrict__ M,  const float* __restrict__ Dl,
                         const float* __restrict__ xm, const float* __restrict__ w_gx,
                         const float* __restrict__ b_gx)
{
    int n = blockIdx.x * blockDim.x + threadIdx.x;
    if (n >= BT * Dd) return;
    int nrow = n >> 7, d = n & 127;
    int t = nrow >> 9, b = nrow & 511;
    int src = (b * Tt + t) * Dd + d;
    float dl = Dl[src];
    float m  = M[src];
    float dx = expf(-fmaxf(dl * w_gx[d] + b_gx[d], 0.f));
    float xi = m * X[src] + (1.f - m) * (dx * XL[src] + (1.f - dx) * xm[t * Dd + d]);
    g_Axh[nrow * 256 + d]       = __float2half(xi);
    g_Axh[nrow * 256 + 128 + d] = __float2half(m);
    g_Adh[nrow * 128 + d]       = __float2half(dl);
}

// ============ big GEMM P = A_x @ Wp + Pb  (M=BT, N=1536, K=256), fp16+ldmatrix, 3-stage ============
__global__ void __launch_bounds__(256, 2) k_gemmP()
{
    extern __shared__ __half smP[];
    __half* As  = smP;                  // [3][128][40] halves
    __half* Bsm = smP + 3 * 128 * 40;   // [3][128][40] halves
    unsigned ab = sm_addr(As), bb = sm_addr(Bsm);

    int tid = threadIdx.x, warp = tid >> 5, lane = tid & 31;
    int g = lane >> 2, tig = lane & 3;
    int wm = (warp >> 2) * 64, wn = (warp & 3) * 32;
    int m0 = blockIdx.y * 128, n0 = blockIdx.x * 128;

    int a_r = (lane & 7) + ((lane >> 3) & 1) * 8;
    int a_k = (lane >> 4) * 8;
    int b_n = (lane & 7) + ((lane >> 4) & 1) * 8;
    int b_k = ((lane >> 3) & 1) * 8;

    float acc[4][4][4];
    #pragma unroll
    for (int i = 0; i < 4; i++)
        #pragma unroll
        for (int j = 0; j < 4; j++)
            #pragma unroll
            for (int q = 0; q < 4; q++) acc[i][j][q] = 0.f;

    #define PREP(s, kb) do { \
        _Pragma("unroll") \
        for (int i_ = 0; i_ < 2; i_++) { \
            int idx_ = tid + i_ * 256, r_ = idx_ >> 2, c_ = (idx_ & 3) * 8; \
            CP_A16(ab + (unsigned)((((s) * 128 + r_) * 40 + c_) * 2), \
                   &g_Axh[(size_t)(m0 + r_) * 256 + (kb) + c_]); \
        } \
        _Pragma("unroll") \
        for (int i_ = 0; i_ < 2; i_++) { \
            int idx_ = tid + i_ * 256, r_ = idx_ >> 2, c_ = (idx_ & 3) * 8; \
            CP_A16(bb + (unsigned)((((s) * 128 + r_) * 40 + c_) * 2), \
                   &g_Wph[(size_t)(n0 + r_) * 256 + (kb) + c_]); \
        } \
        CP_COMMIT(); \
    } while (0)

    PREP(0, 0);
    PREP(1, 32);
    for (int k0 = 0; k0 < 8; k0++) {
        int cur = k0 % 3;
        if (k0 < 6) { CP_WAIT1(); } else { CP_WAIT0(); }
        __syncthreads();
        if (k0 < 6) PREP((k0 + 2) % 3, (k0 + 2) * 32);
        #pragma unroll
        for (int kk = 0; kk < 32; kk += 16) {
            unsigned af[4][4], bf[2][4];
            #pragma unroll
            for (int i = 0; i < 4; i++)
                ldm4(af[i], ab + (unsigned)(((cur * 128 + wm + i * 16 + a_r) * 40
                                             + kk + a_k) * 2));
            #pragma unroll
            for (int jj = 0; jj < 2; jj++)
                ldm4(bf[jj], bb + (unsigned)(((cur * 128 + wn + jj * 16 + b_n) * 40
                                              + kk + b_k) * 2));
            #pragma unroll
            for (int i = 0; i < 4; i++)
                #pragma unroll
                for (int j = 0; j < 4; j++)
                    mma16(acc[i][j], af[i], &bf[j >> 1][(j & 1) * 2]);
        }
    }
    #undef PREP

    #pragma unroll
    for (int i = 0; i < 4; i++) {
        int r0 = m0 + wm + i * 16 + g;
        #pragma unroll
        for (int j = 0; j < 4; j++) {
            int c0 = n0 + wn + j * 8 + 2 * tig;
            float b0 = g_Pb[c0], b1 = g_Pb[c0 + 1];
            float2 v0 = make_float2(acc[i][j][0] + b0, acc[i][j][1] + b1);
            float2 v1 = make_float2(acc[i][j][2] + b0, acc[i][j][3] + b1);
            *(float2*)&g_P[(size_t)r0 * 1536 + c0]       = v0;
            *(float2*)&g_P[(size_t)(r0 + 8) * 1536 + c0] = v1;
        }
    }
}

// ============ DH = exp(-relu(A_d @ Wght + b_gh))  (M=BT, N=512, K=128), fp16+ldmatrix ============
__global__ void __launch_bounds__(256, 2) k_gemmDH(const float* __restrict__ b_gh)
{
    __shared__ __half As[128][40];
    __shared__ __half Bs[128][40];
    unsigned ab = sm_addr(&As[0][0]), bb = sm_addr(&Bs[0][0]);
    int tid = threadIdx.x, warp = tid >> 5, lane = tid & 31;
    int g = lane >> 2, tig = lane & 3;
    int wm = (warp >> 2) * 64, wn = (warp & 3) * 32;
    int m0 = blockIdx.y * 128, n0 = blockIdx.x * 128;

    int a_r = (lane & 7) + ((lane >> 3) & 1) * 8;
    int a_k = (lane >> 4) * 8;
    int b_n = (lane & 7) + ((lane >> 4) & 1) * 8;
    int b_k = ((lane >> 3) & 1) * 8;

    float acc[4][4][4];
    #pragma unroll
    for (int i = 0; i < 4; i++)
        #pragma unroll
        for (int j = 0; j < 4; j++)
            #pragma unroll
            for (int q = 0; q < 4; q++) acc[i][j][q] = 0.f;

    for (int k0 = 0; k0 < 128; k0 += 32) {
        #pragma unroll
        for (int i = 0; i < 2; i++) {
            int idx = tid + i * 256, r = idx >> 2, c = (idx & 3) * 8;
            *(float4*)&As[r][c] =
                *(const float4*)&g_Adh[(size_t)(m0 + r) * 128 + k0 + c];
        }
        #pragma unroll
        for (int i = 0; i < 2; i++) {
            int idx = tid + i * 256, r = idx >> 2, c = (idx & 3) * 8;
            *(float4*)&Bs[r][c] =
                *(const float4*)&g_Wghth[(size_t)(n0 + r) * 128 + k0 + c];
        }
        __syncthreads();
        #pragma unroll
        for (int kk = 0; kk < 32; kk += 16) {
            unsigned af[4][4], bf[2][4];
            #pragma unroll
            for (int i = 0; i < 4; i++)
                ldm4(af[i], ab + (unsigned)(((wm + i * 16 + a_r) * 40 + kk + a_k) * 2));
            #pragma unroll
            for (int jj = 0; jj < 2; jj++)
                ldm4(bf[jj], bb + (unsigned)(((wn + jj * 16 + b_n) * 40 + kk + b_k) * 2));
            #pragma unroll
            for (int i = 0; i < 4; i++)
                #pragma unroll
                for (int j = 0; j < 4; j++)
                    mma16(acc[i][j], af[i], &bf[j >> 1][(j & 1) * 2]);
        }
        __syncthreads();
    }
    #pragma unroll
    for (int i = 0; i < 4; i++) {
        int r0 = m0 + wm + i * 16 + g;
        #pragma unroll
        for (int j = 0; j < 4; j++) {
            int c0 = n0 + wn + j * 8 + 2 * tig;
            float b0 = b_gh[c0], b1 = b_gh[c0 + 1];
            g_DH[(size_t)r0 * 512 + c0]           = expf(-fmaxf(acc[i][j][0] + b0, 0.f));
            g_DH[(size_t)r0 * 512 + c0 + 1]       = expf(-fmaxf(acc[i][j][1] + b1, 0.f));
            g_DH[(size_t)(r0 + 8) * 512 + c0]     = expf(-fmaxf(acc[i][j][2] + b0, 0.f));
            g_DH[(size_t)(r0 + 8) * 512 + c0 + 1] = expf(-fmaxf(acc[i][j][3] + b1, 0.f));
        }
    }
}

// ============ persistent recurrence: 8-CTA clusters, hardware barriers ============
// grid = 128 blocks = 16 rowgroups (clusters) x 8 colblks, 256 threads (8 warps, 2x4)
__global__ void __launch_bounds__(256) __cluster_dims__(8, 1, 1) k_recur()
{
    extern __shared__ __half smR[];
    __half* Wa = smR;                       // [128 n][520 k] phase A weights 133.1 KB
    __half* Wb = smR + 128 * 520;           // [64 n][520 k] phase B weights   66.6 KB
    __half* As = Wb + 64 * 520;             // [4][32][72] activation staging  18.4 KB
    unsigned asb = sm_addr(As);
    unsigned wab = sm_addr(Wa), wbb = sm_addr(Wb);

    int tid = threadIdx.x, warp = tid >> 5, lane = tid & 31;
    int g = lane >> 2, tig = lane & 3;
    int rowgrp = blockIdx.x >> 3, colblk = blockIdx.x & 7;
    int m0 = rowgrp * 32;
    int n0A = colblk * 128, n0B = colblk * 64;

    // ---- load resident weight slices once (n-major, k contiguous) ----
    for (int i = tid; i < 128 * 64; i += 256) {
        int n = i >> 6, c8 = (i & 63) * 8;
        *(float4*)&Wa[n * 520 + c8] =
            *(const float4*)&g_Wzrh[(size_t)(n0A + n) * 512 + c8];
    }
    for (int i = tid; i < 64 * 64; i += 256) {
        int n = i >> 6, c8 = (i & 63) * 8;
        *(float4*)&Wb[n * 520 + c8] =
            *(const float4*)&g_Whhh[(size_t)(n0B + n) * 512 + c8];
    }
    __syncthreads();

    int wm  = (warp >> 2) * 16;          // 0 or 16 (2 row groups of warps)
    int wnA = (warp & 3) * 32;           // phase A warp cols (32 wide)
    int wnB = (warp & 3) * 16;           // phase B warp cols (16 wide)
    bool isz = (colblk < 4);

    // ldmatrix lane address components
    int a_r = (lane & 7) + ((lane >> 3) & 1) * 8;
    int a_k = (lane >> 4) * 8;
    int b_n = (lane & 7) + ((lane >> 4) & 1) * 8;
    int b_k = ((lane >> 3) & 1) * 8;

    for (int t = 0; t < Tt; t++) {
        const float* Pr = g_P + (size_t)t * Bz * 1536;

        // ---------- phase A: z|r = sigmoid(HZ @ Wzr + P_zr), block tile 32x128 ----------
        {
            pre_tile32h(asb, 0, 0,   g_HZh, m0, tid);
            pre_tile32h(asb, 1, 64,  g_HZh, m0, tid);
            pre_tile32h(asb, 2, 128, g_HZh, m0, tid);

            float prf[4][2][2], hzf[4][2][2];
            #pragma unroll
            for (int j = 0; j < 4; j++) {
                int c = n0A + wnA + j * 8 + 2 * tig;
                #pragma unroll
                for (int rr = 0; rr < 2; rr++) {
                    int row = m0 + wm + g + rr * 8;
                    #pragma unroll
                    for (int cc = 0; cc < 2; cc++) {
                        prf[j][rr][cc] = Pr[(size_t)row * 1536 + c + cc];
                        if (!isz) hzf[j][rr][cc] =
                            __half2float(g_HZh[row * 512 + (c + cc - 512)]);
                    }
                }
            }

            float acc[4][4];
            #pragma unroll
            for (int j = 0; j < 4; j++)
                #pragma unroll
                for (int q = 0; q < 4; q++) acc[j][q] = 0.f;

            for (int k0 = 0; k0 < 8; k0++) {
                int cur = k0 & 3;
                if (k0 < 6) { CP_WAIT2(); } else if (k0 == 6) { CP_WAIT1(); } else { CP_WAIT0(); }
                __syncthreads();
                if (k0 < 5) pre_tile32h(asb, (k0 + 3) & 3, (k0 + 3) * 64, g_HZh, m0, tid);
                #pragma unroll
                for (int kk = 0; kk < 64; kk += 16) {
                    int kb = k0 * 64 + kk;
                    unsigned af[4], bf[2][4];
                    ldm4(af, asb + (unsigned)(((cur * 32 + wm + a_r) * 72 + kk + a_k) * 2));
                    #pragma unroll
                    for (int jj = 0; jj < 2; jj++)
                        ldm4(bf[jj], wab + (unsigned)(((wnA + jj * 16 + b_n) * 520
                                                       + kb + b_k) * 2));
                    #pragma unroll
                    for (int j = 0; j < 4; j++)
                        mma16(acc[j], af, &bf[j >> 1][(j & 1) * 2]);
                }
            }

            #pragma unroll
            for (int j = 0; j < 4; j++) {
                int c = n0A + wnA + j * 8 + 2 * tig;
                #pragma unroll
                for (int rr = 0; rr < 2; rr++) {
                    int row = m0 + wm + g + rr * 8;
                    #pragma unroll
                    for (int cc = 0; cc < 2; cc++) {
                        float pre = acc[j][rr * 2 + cc] + prf[j][rr][cc];
                        float s = 1.f / (1.f + expf(-pre));
                        if (isz) {
                            g_Z[row * 512 + c + cc] = s;
                        } else {
                            int jj = c + cc - 512;
                            g_RHh[row * 512 + jj] = __float2half(s * hzf[j][rr][cc]);
                        }
                    }
                }
            }
        }
        CLUSTER_SYNC();

        // ---------- phase B: h update, block tile 32x64 ----------
        {
            pre_tile32h(asb, 0, 0,   g_RHh, m0, tid);
            pre_tile32h(asb, 1, 64,  g_RHh, m0, tid);
            pre_tile32h(asb, 2, 128, g_RHh, m0, tid);

            float prf2[2][2][2], zf[2][2][2], dcf[2][2][2], hpf[2][2][2], dnf[2][2][2];
            const float* dhc = g_DH + (size_t)t * Bz * 512;
            const float* dhn = g_DH + (size_t)(t + 1) * Bz * 512;
            bool notlast = (t < Tt - 1);
            #pragma unroll
            for (int j = 0; j < 2; j++) {
                int c = n0B + wnB + j * 8 + 2 * tig;
                #pragma unroll
                for (int rr = 0; rr < 2; rr++) {
                    int row = m0 + wm + g + rr * 8;
                    #pragma unroll
                    for (int cc = 0; cc < 2; cc++) {
                        int col = c + cc;
                        prf2[j][rr][cc] = Pr[(size_t)row * 1536 + 1024 + col];
                        zf[j][rr][cc]  = g_Z[row * 512 + col];
                        dcf[j][rr][cc] = dhc[row * 512 + col];
                        hpf[j][rr][cc] = g_h[row * 512 + col];
                        if (notlast) dnf[j][rr][cc] = dhn[row * 512 + col];
                    }
                }
            }

            float acc[2][4];
            #pragma unroll
            for (int j = 0; j < 2; j++)
                #pragma unroll
                for (int q = 0; q < 4; q++) acc[j][q] = 0.f;

            for (int k0 = 0; k0 < 8; k0++) {
                int cur = k0 & 3;
                if (k0 < 6) { CP_WAIT2(); } else if (k0 == 6) { CP_WAIT1(); } else { CP_WAIT0(); }
                __syncthreads();
                if (k0 < 5) pre_tile32h(asb, (k0 + 3) & 3, (k0 + 3) * 64, g_RHh, m0, tid);
                #pragma unroll
                for (int kk = 0; kk < 64; kk += 16) {
                    int kb = k0 * 64 + kk;
                    unsigned af[4], bf[4];
                    ldm4(af, asb + (unsigned)(((cur * 32 + wm + a_r) * 72 + kk + a_k) * 2));
                    ldm4(bf, wbb + (unsigned)(((wnB + b_n) * 520 + kb + b_k) * 2));
                    mma16(acc[0], af, &bf[0]);
                    mma16(acc[1], af, &bf[2]);
                }
            }

            #pragma unroll
            for (int j = 0; j < 2; j++) {
                int c = n0B + wnB + j * 8 + 2 * tig;
                #pragma unroll
                for (int rr = 0; rr < 2; rr++) {
                    int row = m0 + wm + g + rr * 8;
                    #pragma unroll
                    for (int cc = 0; cc < 2; cc++) {
                        int col = c + cc;
                        float ht = tanhf(acc[j][rr * 2 + cc] + prf2[j][rr][cc]);
                        float z  = zf[j][rr][cc];
                        float hz = dcf[j][rr][cc] * hpf[j][rr][cc];
                        float hn = (1.f - z) * hz + z * ht;
                        g_h[row * 512 + col] = hn;
                        if (notlast)
                            g_HZh[row * 512 + col] = __float2half(dnf[j][rr][cc] * hn);
                    }
                }
            }
        }
        CLUSTER_SYNC();
    }
}

// ---------------- tail: logits + train-mode BatchNorm over batch ----------------
__global__ void __launch_bounds__(512) k_final(const float* __restrict__ W_fc,
                                               const float* __restrict__ b_fc,
                                               const float* __restrict__ gma,
                                               const float* __restrict__ bta,
                                               float* __restrict__ out)
{
    __shared__ float w0[512], w1[512];
    __shared__ float4 red[512];
    int tid = threadIdx.x;
    w0[tid] = W_fc[tid];
    w1[tid] = W_fc[512 + tid];
    __syncthreads();

    const float4* hr4 = (const float4*)(g_h + (size_t)tid * 512);
    float a0 = 0.f, a1 = 0.f;
    #pragma unroll 8
    for (int k4 = 0; k4 < 128; k4++) {
        float4 v = hr4[k4];
        int k = k4 * 4;
        a0 += v.x * w0[k] + v.y * w0[k + 1] + v.z * w0[k + 2] + v.w * w0[k + 3];
        a1 += v.x * w1[k] + v.y * w1[k + 1] + v.z * w1[k + 2] + v.w * w1[k + 3];
    }
    a0 += b_fc[0];
    a1 += b_fc[1];

    red[tid] = make_float4(a0, a1, a0 * a0, a1 * a1);
    __syncthreads();
    for (int s = 256; s > 0; s >>= 1) {
        if (tid < s) {
            float4 o = red[tid + s];
            red[tid].x += o.x; red[tid].y += o.y;
            red[tid].z += o.z; red[tid].w += o.w;
        }
        __syncthreads();
    }
    float4 tot = red[0];
    float mu0 = tot.x * (1.f / 512.f), mu1 = tot.y * (1.f / 512.f);
    float v0  = tot.z * (1.f / 512.f) - mu0 * mu0;
    float v1  = tot.w * (1.f / 512.f) - mu1 * mu1;
    out[tid * 2 + 0] = gma[0] * (a0 - mu0) * rsqrtf(v0 + 1e-5f) + bta[0];
    out[tid * 2 + 1] = gma[1] * (a1 - mu1) * rsqrtf(v1 + 1e-5f) + bta[1];
}

// ---------------- launcher ----------------
#define SMEM_GEMMP  ((3 * 128 * 40 + 3 * 128 * 40) * 2)            // 61,440 B (2 CTA/SM)
#define SMEM_RECUR  ((128 * 520 + 64 * 520 + 4 * 32 * 72) * 2)     // 218,112 B

extern "C" void kernel_launch(void* const* d_in, const int* in_sizes, int n_in,
                              void* d_out, int out_size)
{
    (void)in_sizes; (void)n_in; (void)out_size;
    const float* X    = (const float*)d_in[0];
    const float* XL   = (const float*)d_in[1];
    const float* Mk   = (const float*)d_in[2];
    const float* Dl   = (const float*)d_in[3];
    const float* xm   = (const float*)d_in[4];
    const float* w_gx = (const float*)d_in[5];
    const float* b_gx = (const float*)d_in[6];
    const float* W_gh = (const float*)d_in[7];
    const float* b_gh = (const float*)d_in[8];
    const float* W_z  = (const float*)d_in[9];
    const float* b_z  = (const float*)d_in[10];
    const float* W_r  = (const float*)d_in[11];
    const float* b_r  = (const float*)d_in[12];
    const float* W_h  = (const float*)d_in[13];
    const float* b_h  = (const float*)d_in[14];
    const float* W_fc = (const float*)d_in[15];
    const float* b_fc = (const float*)d_in[16];
    const float* gma  = (const float*)d_in[17];
    const float* bta  = (const float*)d_in[18];
    float* out = (float*)d_out;

    static int attr_done = 0;
    if (!attr_done) {
        cudaFuncSetAttribute(k_gemmP, cudaFuncAttributeMaxDynamicSharedMemorySize, SMEM_GEMMP);
        cudaFuncSetAttribute(k_recur, cudaFuncAttributeMaxDynamicSharedMemorySize, SMEM_RECUR);
        attr_done = 1;
    }

    k_pack<<<768, 256>>>(W_z, b_z, W_r, b_r, W_h, b_h, W_gh);
    k_impute<<<(BT * Dd + 255) / 256, 256>>>(X, XL, Mk, Dl, xm, w_gx, b_gx);
    k_gemmP <<<dim3(1536 / 128, BT / 128), 256, SMEM_GEMMP>>>();
    k_gemmDH<<<dim3(512 / 128,  BT / 128), 256>>>(b_gh);
    k_recur <<<NBLK, 256, SMEM_RECUR>>>();
    k_final <<<1, 512>>>(W_fc, b_fc, gma, bta, out);
}

// round 17
// speedup vs baseline: 1.5020x; 1.5020x over previous
#include <cuda_runtime.h>
#include <cuda_fp16.h>
#include <math.h>

// Problem constants
#define Bz 512
#define Tt 200
#define Dd 128
#define Hh 512
#define BT (Bz * Tt)          // 102400
#define COMB 768
#define NBLK 128              // persistent grid: 1 block/SM

// ---------------- scratch (static device globals) ----------------
__device__ __half g_Axh [BT * 256];       // [x_imp || mask], fp16
__device__ __half g_Adh [BT * 128];       // Delta, fp16
__device__ float  g_P  [BT * 1536];       // gate pre-acts (fp32)
__device__ float  g_DH [BT * Hh];         // delta_h (fp32)
__device__ __half g_Wph [1536 * 256];     // packed [x;m] weights, n-major [n][k]
__device__ float  g_Pb [1536];
__device__ __half g_Wghth[512 * 128];     // W_gh, n-major [n][k]
__device__ __half g_Wzrh [1024 * 512];    // h-part W_z|W_r, n-major
__device__ __half g_Whhh [512 * 512];     // h-part W_h, n-major
__device__ float  g_Z  [Bz * Hh];         // z gate (fp32)
__device__ __half g_RHh[Bz * Hh];         // r*(dh*h), fp16
__device__ __half g_HZh[Bz * Hh];         // dh_t * h_{t-1}, fp16
__device__ float  g_h  [Bz * Hh];         // hidden state (exact fp32)

// per-rowgroup barrier state (8 groups, 128B-separated slots)
__device__ unsigned g_cnt2[8 * 32];
__device__ volatile unsigned g_gen2[8 * 32];

// ---------------- helpers ----------------
__device__ __forceinline__ void mma16(float* d, const unsigned* a, const unsigned* b) {
    asm volatile(
        "mma.sync.aligned.m16n8k16.row.col.f32.f16.f16.f32 "
        "{%0,%1,%2,%3},{%4,%5,%6,%7},{%8,%9},{%0,%1,%2,%3};"
        : "+f"(d[0]), "+f"(d[1]), "+f"(d[2]), "+f"(d[3])
        : "r"(a[0]), "r"(a[1]), "r"(a[2]), "r"(a[3]),
          "r"(b[0]), "r"(b[1]));
}
__device__ __forceinline__ void ldm4(unsigned* r, unsigned addr) {
    asm volatile("ldmatrix.sync.aligned.m8n8.x4.shared.b16 {%0,%1,%2,%3}, [%4];"
        : "=r"(r[0]), "=r"(r[1]), "=r"(r[2]), "=r"(r[3]) : "r"(addr));
}
__device__ __forceinline__ void ldm2(unsigned* r, unsigned addr) {
    asm volatile("ldmatrix.sync.aligned.m8n8.x2.shared.b16 {%0,%1}, [%2];"
        : "=r"(r[0]), "=r"(r[1]) : "r"(addr));
}
__device__ __forceinline__ unsigned sm_addr(const void* p) {
    unsigned a;
    asm("{.reg .u64 t; cvta.to.shared.u64 t, %1; cvt.u32.u64 %0, t;}" : "=r"(a) : "l"(p));
    return a;
}
#define CP_A16(dst, src) asm volatile("cp.async.ca.shared.global [%0], [%1], 16;" :: "r"(dst), "l"(src))
#define CP_COMMIT()      asm volatile("cp.async.commit_group;")
#define CP_WAIT1()       asm volatile("cp.async.wait_group 1;")
#define CP_WAIT0()       asm volatile("cp.async.wait_group 0;")

// barrier among the 16 blocks of one rowgroup
__device__ __forceinline__ void groupbar(int grp, unsigned &gen) {
    __syncthreads();
    if (threadIdx.x == 0) {
        __threadfence();
        unsigned t = atomicAdd(&g_cnt2[grp * 32], 1u);
        if (t == 15) {
            g_cnt2[grp * 32] = 0;
            __threadfence();
            atomicAdd((unsigned*)&g_gen2[grp * 32], 1u);
        } else {
            while (g_gen2[grp * 32] == gen) { }
        }
        __threadfence();
    }
    gen++;
    __syncthreads();
}

// single-shot prefetch of a full 64x512(half) activation tile (stride 520 halves)
__device__ __forceinline__ void pre_full(unsigned asb, const __half* __restrict__ src,
                                         int m0, int tid) {
    #pragma unroll
    for (int i = 0; i < 16; i++) {
        int idx = tid + i * 256;            // 4096 chunks: 64 rows x 64 chunks of 8 halves
        int r = idx >> 6, c = (idx & 63) * 8;
        CP_A16(asb + (unsigned)((r * 520 + c) * 2),
               &src[(size_t)(m0 + r) * 512 + c]);
    }
    CP_COMMIT();
}

// ---------------- weight packing (fp16, n-major) + state init ----------------
__global__ void k_pack(const float* __restrict__ W_z, const float* __restrict__ b_z,
                       const float* __restrict__ W_r, const float* __restrict__ b_r,
                       const float* __restrict__ W_h, const float* __restrict__ b_h,
                       const float* __restrict__ W_gh)
{
    int tid = blockIdx.x * blockDim.x + threadIdx.x;
    int nt  = gridDim.x * blockDim.x;

    for (int idx = tid; idx < 1536 * 256; idx += nt) {
        int n = idx >> 8, k = idx & 255;
        int gsel = n >> 9, jj = n & 511;
        const float* W = (gsel == 0) ? W_z : (gsel == 1) ? W_r : W_h;
        int col = (k < 128) ? k : (640 + (k - 128));
        g_Wph[idx] = __float2half(W[jj * COMB + col]);
    }
    for (int j = tid; j < 1536; j += nt) {
        int gsel = j >> 9, jj = j & 511;
        g_Pb[j] = (gsel == 0) ? b_z[jj] : (gsel == 1) ? b_r[jj] : b_h[jj];
    }
    for (int idx = tid; idx < 512 * 128; idx += nt)
        g_Wghth[idx] = __float2half(W_gh[idx]);           // already [n][k]
    for (int idx = tid; idx < 1024 * 512; idx += nt) {
        int n = idx >> 9, k = idx & 511;
        g_Wzrh[idx] = __float2half((n < 512) ? W_z[n * COMB + 128 + k]
                                             : W_r[(n - 512) * COMB + 128 + k]);
    }
    for (int idx = tid; idx < 512 * 512; idx += nt) {
        int n = idx >> 9, k = idx & 511;
        g_Whhh[idx] = __float2half(W_h[n * COMB + 128 + k]);
    }
    for (int idx = tid; idx < Bz * Hh; idx += nt) {
        g_h[idx] = 0.f;
        g_HZh[idx] = __float2half(0.f);
    }
}

// ---------------- imputation (fp16 stores) ----------------
__global__ void k_impute(const float* __restrict__ X,  const float* __restrict__ XL,
                         const float* __restrict__ M,  const float* __restrict__ Dl,
                         const float* __restrict__ xm, const float* __restrict__ w_gx,
                         const float* __restrict__ b_gx)
{
    int n = blockIdx.x * blockDim.x + threadIdx.x;
    if (n >= BT * Dd) return;
    int nrow = n >> 7, d = n & 127;
    int t = nrow >> 9, b = nrow & 511;
    int src = (b * Tt + t) * Dd + d;
    float dl = Dl[src];
    float m  = M[src];
    float dx = expf(-fmaxf(dl * w_gx[d] + b_gx[d], 0.f));
    float xi = m * X[src] + (1.f - m) * (dx * XL[src] + (1.f - dx) * xm[t * Dd + d]);
    g_Axh[nrow * 256 + d]       = __float2half(xi);
    g_Axh[nrow * 256 + 128 + d] = __float2half(m);
    g_Adh[nrow * 128 + d]       = __float2half(dl);
}

// ============ big GEMM P = A_x @ Wp + Pb  (M=BT, N=1536, K=256), fp16+ldmatrix, 3-stage ============
__global__ void __launch_bounds__(256, 2) k_gemmP()
{
    extern __shared__ __half smP[];
    __half* As  = smP;                  // [3][128][40] halves
    __half* Bsm = smP + 3 * 128 * 40;   // [3][128][40] halves
    unsigned ab = sm_addr(As), bb = sm_addr(Bsm);

    int tid = threadIdx.x, warp = tid >> 5, lane = tid & 31;
    int g = lane >> 2, tig = lane & 3;
    int wm = (warp >> 2) * 64, wn = (warp & 3) * 32;
    int m0 = blockIdx.y * 128, n0 = blockIdx.x * 128;

    int a_r = (lane & 7) + ((lane >> 3) & 1) * 8;
    int a_k = (lane >> 4) * 8;
    int b_n = (lane & 7) + ((lane >> 4) & 1) * 8;
    int b_k = ((lane >> 3) & 1) * 8;

    float acc[4][4][4];
    #pragma unroll
    for (int i = 0; i < 4; i++)
        #pragma unroll
        for (int j = 0; j < 4; j++)
            #pragma unroll
            for (int q = 0; q < 4; q++) acc[i][j][q] = 0.f;

    #define PREP(s, kb) do { \
        _Pragma("unroll") \
        for (int i_ = 0; i_ < 2; i_++) { \
            int idx_ = tid + i_ * 256, r_ = idx_ >> 2, c_ = (idx_ & 3) * 8; \
            CP_A16(ab + (unsigned)((((s) * 128 + r_) * 40 + c_) * 2), \
                   &g_Axh[(size_t)(m0 + r_) * 256 + (kb) + c_]); \
        } \
        _Pragma("unroll") \
        for (int i_ = 0; i_ < 2; i_++) { \
            int idx_ = tid + i_ * 256, r_ = idx_ >> 2, c_ = (idx_ & 3) * 8; \
            CP_A16(bb + (unsigned)((((s) * 128 + r_) * 40 + c_) * 2), \
                   &g_Wph[(size_t)(n0 + r_) * 256 + (kb) + c_]); \
        } \
        CP_COMMIT(); \
    } while (0)

    PREP(0, 0);
    PREP(1, 32);
    for (int k0 = 0; k0 < 8; k0++) {
        int cur = k0 % 3;
        if (k0 < 6) { CP_WAIT1(); } else { CP_WAIT0(); }
        __syncthreads();
        if (k0 < 6) PREP((k0 + 2) % 3, (k0 + 2) * 32);
        #pragma unroll
        for (int kk = 0; kk < 32; kk += 16) {
            unsigned af[4][4], bf[2][4];
            #pragma unroll
            for (int i = 0; i < 4; i++)
                ldm4(af[i], ab + (unsigned)(((cur * 128 + wm + i * 16 + a_r) * 40
                                             + kk + a_k) * 2));
            #pragma unroll
            for (int jj = 0; jj < 2; jj++)
                ldm4(bf[jj], bb + (unsigned)(((cur * 128 + wn + jj * 16 + b_n) * 40
                                              + kk + b_k) * 2));
            #pragma unroll
            for (int i = 0; i < 4; i++)
                #pragma unroll
                for (int j = 0; j < 4; j++)
                    mma16(acc[i][j], af[i], &bf[j >> 1][(j & 1) * 2]);
        }
    }
    #undef PREP

    #pragma unroll
    for (int i = 0; i < 4; i++) {
        int r0 = m0 + wm + i * 16 + g;
        #pragma unroll
        for (int j = 0; j < 4; j++) {
            int c0 = n0 + wn + j * 8 + 2 * tig;
            float b0 = g_Pb[c0], b1 = g_Pb[c0 + 1];
            float2 v0 = make_float2(acc[i][j][0] + b0, acc[i][j][1] + b1);
            float2 v1 = make_float2(acc[i][j][2] + b0, acc[i][j][3] + b1);
            *(float2*)&g_P[(size_t)r0 * 1536 + c0]       = v0;
            *(float2*)&g_P[(size_t)(r0 + 8) * 1536 + c0] = v1;
        }
    }
}

// ============ DH = exp(-relu(A_d @ Wght + b_gh))  (M=BT, N=512, K=128), fp16+ldmatrix ============
__global__ void __launch_bounds__(256, 2) k_gemmDH(const float* __restrict__ b_gh)
{
    __shared__ __half As[128][40];
    __shared__ __half Bs[128][40];
    unsigned ab = sm_addr(&As[0][0]), bb = sm_addr(&Bs[0][0]);
    int tid = threadIdx.x, warp = tid >> 5, lane = tid & 31;
    int g = lane >> 2, tig = lane & 3;
    int wm = (warp >> 2) * 64, wn = (warp & 3) * 32;
    int m0 = blockIdx.y * 128, n0 = blockIdx.x * 128;

    int a_r = (lane & 7) + ((lane >> 3) & 1) * 8;
    int a_k = (lane >> 4) * 8;
    int b_n = (lane & 7) + ((lane >> 4) & 1) * 8;
    int b_k = ((lane >> 3) & 1) * 8;

    float acc[4][4][4];
    #pragma unroll
    for (int i = 0; i < 4; i++)
        #pragma unroll
        for (int j = 0; j < 4; j++)
            #pragma unroll
            for (int q = 0; q < 4; q++) acc[i][j][q] = 0.f;

    for (int k0 = 0; k0 < 128; k0 += 32) {
        #pragma unroll
        for (int i = 0; i < 2; i++) {
            int idx = tid + i * 256, r = idx >> 2, c = (idx & 3) * 8;
            *(float4*)&As[r][c] =
                *(const float4*)&g_Adh[(size_t)(m0 + r) * 128 + k0 + c];
        }
        #pragma unroll
        for (int i = 0; i < 2; i++) {
            int idx = tid + i * 256, r = idx >> 2, c = (idx & 3) * 8;
            *(float4*)&Bs[r][c] =
                *(const float4*)&g_Wghth[(size_t)(n0 + r) * 128 + k0 + c];
        }
        __syncthreads();
        #pragma unroll
        for (int kk = 0; kk < 32; kk += 16) {
            unsigned af[4][4], bf[2][4];
            #pragma unroll
            for (int i = 0; i < 4; i++)
                ldm4(af[i], ab + (unsigned)(((wm + i * 16 + a_r) * 40 + kk + a_k) * 2));
            #pragma unroll
            for (int jj = 0; jj < 2; jj++)
                ldm4(bf[jj], bb + (unsigned)(((wn + jj * 16 + b_n) * 40 + kk + b_k) * 2));
            #pragma unroll
            for (int i = 0; i < 4; i++)
                #pragma unroll
                for (int j = 0; j < 4; j++)
                    mma16(acc[i][j], af[i], &bf[j >> 1][(j & 1) * 2]);
        }
        __syncthreads();
    }
    #pragma unroll
    for (int i = 0; i < 4; i++) {
        int r0 = m0 + wm + i * 16 + g;
        #pragma unroll
        for (int j = 0; j < 4; j++) {
            int c0 = n0 + wn + j * 8 + 2 * tig;
            float b0 = b_gh[c0], b1 = b_gh[c0 + 1];
            g_DH[(size_t)r0 * 512 + c0]           = expf(-fmaxf(acc[i][j][0] + b0, 0.f));
            g_DH[(size_t)r0 * 512 + c0 + 1]       = expf(-fmaxf(acc[i][j][1] + b1, 0.f));
            g_DH[(size_t)(r0 + 8) * 512 + c0]     = expf(-fmaxf(acc[i][j][2] + b0, 0.f));
            g_DH[(size_t)(r0 + 8) * 512 + c0 + 1] = expf(-fmaxf(acc[i][j][3] + b1, 0.f));
        }
    }
}

// ============ persistent recurrence: single-shot activation loads, 1 sync gate/phase ============
// grid = 128 blocks (8 rowgroups x 16 col), 256 threads (8 warps, 2x4 warp grid)
__global__ void __launch_bounds__(256) k_recur()
{
    extern __shared__ __half smR[];
    __half* Wa = smR;                       // [64 n][520 k] phase A weights  66.6 KB
    __half* Wb = smR + 64 * 520;            // [32 n][520 k] phase B weights  33.3 KB
    __half* As = Wb + 32 * 520;             // [64 m][520 k] activation tile  66.6 KB
    unsigned asb = sm_addr(As);
    unsigned wab = sm_addr(Wa), wbb = sm_addr(Wb);

    int tid = threadIdx.x, warp = tid >> 5, lane = tid & 31;
    int g = lane >> 2, tig = lane & 3;
    int rowblk = blockIdx.x >> 4, colblk = blockIdx.x & 15;
    int m0 = rowblk * 64;
    int n0A = colblk * 64, n0B = colblk * 32;
    unsigned gen = g_gen2[rowblk * 32];

    // ---- load resident weight slices once (n-major, k contiguous) ----
    for (int i = tid; i < 64 * 64; i += 256) {
        int n = i >> 6, c8 = (i & 63) * 8;
        *(float4*)&Wa[n * 520 + c8] =
            *(const float4*)&g_Wzrh[(size_t)(n0A + n) * 512 + c8];
    }
    for (int i = tid; i < 32 * 64; i += 256) {
        int n = i >> 6, c8 = (i & 63) * 8;
        *(float4*)&Wb[n * 520 + c8] =
            *(const float4*)&g_Whhh[(size_t)(n0B + n) * 512 + c8];
    }
    __syncthreads();

    int wm  = (warp >> 2) * 32;
    int wnA = (warp & 3) * 16;
    int wnB = (warp & 3) * 8;
    bool isz = (colblk < 8);

    // ldmatrix lane address components
    int a_r = (lane & 7) + ((lane >> 3) & 1) * 8;
    int a_k = (lane >> 4) * 8;
    int b_n = (lane & 7) + ((lane >> 4) & 1) * 8;
    int b_k = ((lane >> 3) & 1) * 8;
    int b2_n = (lane & 7);                       // x2 variant (lanes 0-15 used)
    int b2_k = ((lane >> 3) & 1) * 8;

    for (int t = 0; t < Tt; t++) {
        const float* Pr = g_P + (size_t)t * Bz * 1536;

        // ---------- phase A: z|r = sigmoid(HZ @ Wzr + P_zr), block tile 64x64 ----------
        {
            pre_full(asb, g_HZh, m0, tid);     // all 64KB in flight

            float prf[2][2][2][2], hzf[2][2][2][2];
            #pragma unroll
            for (int i = 0; i < 2; i++)
                #pragma unroll
                for (int j = 0; j < 2; j++) {
                    int c = n0A + wnA + j * 8 + 2 * tig;
                    #pragma unroll
                    for (int rr = 0; rr < 2; rr++) {
                        int row = m0 + wm + i * 16 + g + rr * 8;
                        #pragma unroll
                        for (int cc = 0; cc < 2; cc++) {
                            prf[i][j][rr][cc] = Pr[(size_t)row * 1536 + c + cc];
                            if (!isz) hzf[i][j][rr][cc] =
                                __half2float(g_HZh[row * 512 + (c + cc - 512)]);
                        }
                    }
                }

            float acc[2][2][4];
            #pragma unroll
            for (int i = 0; i < 2; i++)
                #pragma unroll
                for (int j = 0; j < 2; j++)
                    #pragma unroll
                    for (int q = 0; q < 4; q++) acc[i][j][q] = 0.f;

            CP_WAIT0();
            __syncthreads();

            #pragma unroll 8
            for (int kb = 0; kb < 512; kb += 16) {
                unsigned af[2][4], bf[4];
                #pragma unroll
                for (int i = 0; i < 2; i++)
                    ldm4(af[i], asb + (unsigned)(((wm + i * 16 + a_r) * 520
                                                  + kb + a_k) * 2));
                ldm4(bf, wab + (unsigned)(((wnA + b_n) * 520 + kb + b_k) * 2));
                #pragma unroll
                for (int i = 0; i < 2; i++) {
                    mma16(acc[i][0], af[i], &bf[0]);
                    mma16(acc[i][1], af[i], &bf[2]);
                }
            }

            #pragma unroll
            for (int i = 0; i < 2; i++) {
                #pragma unroll
                for (int j = 0; j < 2; j++) {
                    int c = n0A + wnA + j * 8 + 2 * tig;
                    #pragma unroll
                    for (int rr = 0; rr < 2; rr++) {
                        int row = m0 + wm + i * 16 + g + rr * 8;
                        #pragma unroll
                        for (int cc = 0; cc < 2; cc++) {
                            float pre = acc[i][j][rr * 2 + cc] + prf[i][j][rr][cc];
                            float s = 1.f / (1.f + expf(-pre));
                            if (isz) {
                                g_Z[row * 512 + c + cc] = s;
                            } else {
                                int jj = c + cc - 512;
                                g_RHh[row * 512 + jj] =
                                    __float2half(s * hzf[i][j][rr][cc]);
                            }
                        }
                    }
                }
            }
        }
        groupbar(rowblk, gen);

        // ---------- phase B: h update, block tile 64x32 ----------
        {
            pre_full(asb, g_RHh, m0, tid);

            float prf2[2][2][2], zf[2][2][2], dcf[2][2][2], hpf[2][2][2], dnf[2][2][2];
            const float* dhc = g_DH + (size_t)t * Bz * 512;
            const float* dhn = g_DH + (size_t)(t + 1) * Bz * 512;
            bool notlast = (t < Tt - 1);
            #pragma unroll
            for (int i = 0; i < 2; i++) {
                int c = n0B + wnB + 2 * tig;
                #pragma unroll
                for (int rr = 0; rr < 2; rr++) {
                    int row = m0 + wm + i * 16 + g + rr * 8;
                    #pragma unroll
                    for (int cc = 0; cc < 2; cc++) {
                        int col = c + cc;
                        prf2[i][rr][cc] = Pr[(size_t)row * 1536 + 1024 + col];
                        zf[i][rr][cc]  = g_Z[row * 512 + col];
                        dcf[i][rr][cc] = dhc[row * 512 + col];
                        hpf[i][rr][cc] = g_h[row * 512 + col];
                        if (notlast) dnf[i][rr][cc] = dhn[row * 512 + col];
                    }
                }
            }

            float acc[2][4];
            #pragma unroll
            for (int i = 0; i < 2; i++)
                #pragma unroll
                for (int q = 0; q < 4; q++) acc[i][q] = 0.f;

            CP_WAIT0();
            __syncthreads();

            #pragma unroll 8
            for (int kb = 0; kb < 512; kb += 16) {
                unsigned af[2][4], bf[2];
                #pragma unroll
                for (int i = 0; i < 2; i++)
                    ldm4(af[i], asb + (unsigned)(((wm + i * 16 + a_r) * 520
                                                  + kb + a_k) * 2));
                ldm2(bf, wbb + (unsigned)(((wnB + b2_n) * 520 + kb + b2_k) * 2));
                #pragma unroll
                for (int i = 0; i < 2; i++) mma16(acc[i], af[i], bf);
            }

            #pragma unroll
            for (int i = 0; i < 2; i++) {
                int c = n0B + wnB + 2 * tig;
                #pragma unroll
                for (int rr = 0; rr < 2; rr++) {
                    int row = m0 + wm + i * 16 + g + rr * 8;
                    #pragma unroll
                    for (int cc = 0; cc < 2; cc++) {
                        int col = c + cc;
                        float ht = tanhf(acc[i][rr * 2 + cc] + prf2[i][rr][cc]);
                        float z  = zf[i][rr][cc];
                        float hz = dcf[i][rr][cc] * hpf[i][rr][cc];
                        float hn = (1.f - z) * hz + z * ht;
                        g_h[row * 512 + col] = hn;
                        if (notlast)
                            g_HZh[row * 512 + col] = __float2half(dnf[i][rr][cc] * hn);
                    }
                }
            }
        }
        groupbar(rowblk, gen);
    }
}

// ---------------- tail: logits + train-mode BatchNorm over batch ----------------
__global__ void __launch_bounds__(512) k_final(const float* __restrict__ W_fc,
                                               const float* __restrict__ b_fc,
                                               const float* __restrict__ gma,
                                               const float* __restrict__ bta,
                                               float* __restrict__ out)
{
    __shared__ float w0[512], w1[512];
    __shared__ float4 red[512];
    int tid = threadIdx.x;
    w0[tid] = W_fc[tid];
    w1[tid] = W_fc[512 + tid];
    __syncthreads();

    const float4* hr4 = (const float4*)(g_h + (size_t)tid * 512);
    float a0 = 0.f, a1 = 0.f;
    #pragma unroll 8
    for (int k4 = 0; k4 < 128; k4++) {
        float4 v = hr4[k4];
        int k = k4 * 4;
        a0 += v.x * w0[k] + v.y * w0[k + 1] + v.z * w0[k + 2] + v.w * w0[k + 3];
        a1 += v.x * w1[k] + v.y * w1[k + 1] + v.z * w1[k + 2] + v.w * w1[k + 3];
    }
    a0 += b_fc[0];
    a1 += b_fc[1];

    red[tid] = make_float4(a0, a1, a0 * a0, a1 * a1);
    __syncthreads();
    for (int s = 256; s > 0; s >>= 1) {
        if (tid < s) {
            float4 o = red[tid + s];
            red[tid].x += o.x; red[tid].y += o.y;
            red[tid].z += o.z; red[tid].w += o.w;
        }
        __syncthreads();
    }
    float4 tot = red[0];
    float mu0 = tot.x * (1.f / 512.f), mu1 = tot.y * (1.f / 512.f);
    float v0  = tot.z * (1.f / 512.f) - mu0 * mu0;
    float v1  = tot.w * (1.f / 512.f) - mu1 * mu1;
    out[tid * 2 + 0] = gma[0] * (a0 - mu0) * rsqrtf(v0 + 1e-5f) + bta[0];
    out[tid * 2 + 1] = gma[1] * (a1 - mu1) * rsqrtf(v1 + 1e-5f) + bta[1];
}

// ---------------- launcher ----------------
#define SMEM_GEMMP  ((3 * 128 * 40 + 3 * 128 * 40) * 2)          // 61,440 B (2 CTA/SM)
#define SMEM_RECUR  ((64 * 520 + 32 * 520 + 64 * 520) * 2)       // 166,400 B

extern "C" void kernel_launch(void* const* d_in, const int* in_sizes, int n_in,
                              void* d_out, int out_size)
{
    (void)in_sizes; (void)n_in; (void)out_size;
    const float* X    = (const float*)d_in[0];
    const float* XL   = (const float*)d_in[1];
    const float* Mk   = (const float*)d_in[2];
    const float* Dl   = (const float*)d_in[3];
    const float* xm   = (const float*)d_in[4];
    const float* w_gx = (const float*)d_in[5];
    const float* b_gx = (const float*)d_in[6];
    const float* W_gh = (const float*)d_in[7];
    const float* b_gh = (const float*)d_in[8];
    const float* W_z  = (const float*)d_in[9];
    const float* b_z  = (const float*)d_in[10];
    const float* W_r  = (const float*)d_in[11];
    const float* b_r  = (const float*)d_in[12];
    const float* W_h  = (const float*)d_in[13];
    const float* b_h  = (const float*)d_in[14];
    const float* W_fc = (const float*)d_in[15];
    const float* b_fc = (const float*)d_in[16];
    const float* gma  = (const float*)d_in[17];
    const float* bta  = (const float*)d_in[18];
    float* out = (float*)d_out;

    static int attr_done = 0;
    if (!attr_done) {
        cudaFuncSetAttribute(k_gemmP, cudaFuncAttributeMaxDynamicSharedMemorySize, SMEM_GEMMP);
        cudaFuncSetAttribute(k_recur, cudaFuncAttributeMaxDynamicSharedMemorySize, SMEM_RECUR);
        attr_done = 1;
    }

    k_pack<<<768, 256>>>(W_z, b_z, W_r, b_r, W_h, b_h, W_gh);
    k_impute<<<(BT * Dd + 255) / 256, 256>>>(X, XL, Mk, Dl, xm, w_gx, b_gx);
    k_gemmP <<<dim3(1536 / 128, BT / 128), 256, SMEM_GEMMP>>>();
    k_gemmDH<<<dim3(512 / 128,  BT / 128), 256>>>(b_gh);
    k_recur <<<NBLK, 256, SMEM_RECUR>>>();
    k_final <<<1, 512>>>(W_fc, b_fc, gma, bta, out);
}